// round 7
// baseline (speedup 1.0000x reference)
#include <cuda_runtime.h>
#include <cuda_bf16.h>
#include <cstdint>
#include <math.h>

// ============================================================================
// Tree-GRU via mma.sync (HMMA) bf16 3-term split GEMMs.  B=32, L=4096, D=256.
// R7: 4-deep KC=32 pipeline w/ precomputed staging; prep fused into epilogue.
// A = [x | h] (K=512) bf16 hi/lo;  W = [term][dblk][192][512] bf16.
// Gate warps (nb): r(all K), z(all K), i_n(K<256), h_n(K>=256).
// ============================================================================

#define DH 256
#define MROWS_MAX 65536
#define ASTRIDE ((size_t)MROWS_MAX * 512)          // elems per term
#define ABYTES  (ASTRIDE * 2)                      // bytes per term
#define WSTRIDE ((size_t)4 * 192 * 512)
#define WBYTES  (WSTRIDE * 2)

__device__ __nv_bfloat16 g_A1[2 * ASTRIDE];    // [term][m][512]
__device__ __nv_bfloat16 g_A2a[2 * ASTRIDE];
__device__ __nv_bfloat16 g_A2b[2 * ASTRIDE];
__device__ __nv_bfloat16 g_Wb[2 * WSTRIDE];

// ---------------- PTX helpers ----------------
__device__ __forceinline__ uint32_t smem_u32(const void* p) {
    uint32_t a;
    asm("{ .reg .u64 t; cvta.to.shared.u64 t, %1; cvt.u32.u64 %0, t; }"
        : "=r"(a) : "l"(p));
    return a;
}
__device__ __forceinline__ void cpasync16(uint32_t dst, const void* src) {
    asm volatile("cp.async.cg.shared.global [%0], [%1], 16;"
                 :: "r"(dst), "l"(src) : "memory");
}
__device__ __forceinline__ void cpcommit() {
    asm volatile("cp.async.commit_group;" ::: "memory");
}
template<int N>
__device__ __forceinline__ void cpwait() {
    asm volatile("cp.async.wait_group %0;" :: "n"(N) : "memory");
}
__device__ __forceinline__ void ldsm4(uint32_t r[4], uint32_t addr) {
    asm volatile("ldmatrix.sync.aligned.m8n8.x4.shared.b16 {%0,%1,%2,%3}, [%4];"
                 : "=r"(r[0]), "=r"(r[1]), "=r"(r[2]), "=r"(r[3]) : "r"(addr));
}
__device__ __forceinline__ void mma16816(float c[4], const uint32_t a[4],
                                         uint32_t b0, uint32_t b1) {
    asm volatile("mma.sync.aligned.m16n8k16.row.col.f32.bf16.bf16.f32 "
                 "{%0,%1,%2,%3}, {%4,%5,%6,%7}, {%8,%9}, {%0,%1,%2,%3};"
                 : "+f"(c[0]), "+f"(c[1]), "+f"(c[2]), "+f"(c[3])
                 : "r"(a[0]), "r"(a[1]), "r"(a[2]), "r"(a[3]),
                   "r"(b0), "r"(b1));
}
#define SW64(x) ((x) ^ (((x) >> 3) & 0x30))

// ---------------- math helpers ----------------
__device__ __forceinline__ float sigacc(float x) { return 1.f / (1.f + expf(-x)); }
__device__ __forceinline__ float tanhacc(float x) {
    float ax = fabsf(x);
    float t = expf(-2.f * ax);
    float r = (1.f - t) / (1.f + t);
    return (x < 0.f) ? -r : r;
}
__device__ __forceinline__ uint32_t pk2(float a, float b) {
    __nv_bfloat162 h = __floats2bfloat162_rn(a, b);
    return *(uint32_t*)&h;
}
__device__ __forceinline__ float2 ub2(uint32_t u) {
    __nv_bfloat162 h = *(__nv_bfloat162*)&u;
    return make_float2(__bfloat162float(h.x), __bfloat162float(h.y));
}
__device__ __forceinline__ void split1(float v, float& hi, float& lo) {
    __nv_bfloat16 h = __float2bfloat16(v);
    hi = __bfloat162float(h);
    lo = v - hi;
}
__device__ __forceinline__ void split4(float4 v, uint2& hi, uint2& lo) {
    float hx, lx, hy, ly, hz, lz, hw, lw;
    split1(v.x, hx, lx); split1(v.y, hy, ly);
    split1(v.z, hz, lz); split1(v.w, hw, lw);
    hi = make_uint2(pk2(hx, hy), pk2(hz, hw));
    lo = make_uint2(pk2(lx, ly), pk2(lz, lw));
}
// write 16 floats as bf16 hi (32B at p) + lo (32B at p+ABYTES)
__device__ __forceinline__ void wsplit16(char* p, const float* v) {
    #pragma unroll
    for (int h = 0; h < 2; ++h) {
        uint4 vh, vl;
        uint32_t* ph = &vh.x;
        uint32_t* pl = &vl.x;
        #pragma unroll
        for (int q = 0; q < 4; ++q) {
            float a_hi, a_lo, b_hi, b_lo;
            split1(v[h * 8 + 2 * q], a_hi, a_lo);
            split1(v[h * 8 + 2 * q + 1], b_hi, b_lo);
            ph[q] = pk2(a_hi, b_hi);
            pl[q] = pk2(a_lo, b_lo);
        }
        *(uint4*)(p + h * 16) = vh;
        *(uint4*)(p + ABYTES + h * 16) = vl;
    }
}
// read 16 dims of hi+lo split back to fp32
__device__ __forceinline__ void rsplit16(const char* p, float* v) {
    #pragma unroll
    for (int h = 0; h < 2; ++h) {
        uint4 vh = *(const uint4*)(p + h * 16);
        uint4 vl = *(const uint4*)(p + ABYTES + h * 16);
        const uint32_t* ph = &vh.x;
        const uint32_t* pl = &vl.x;
        #pragma unroll
        for (int q = 0; q < 4; ++q) {
            float2 a = ub2(ph[q]), b = ub2(pl[q]);
            v[h * 8 + 2 * q]     = a.x + b.x;
            v[h * 8 + 2 * q + 1] = a.y + b.y;
        }
    }
}

// ---------------- weight prep: g_Wb[term][dblk][gate*64+dd][k] ----------------
__global__ void wprep(const float* __restrict__ wih, const float* __restrict__ whh) {
    int idx = blockIdx.x * blockDim.x + threadIdx.x;
    if (idx >= 4 * 192 * 512) return;
    int k = idx & 511;
    int rowall = idx >> 9;
    int blk = rowall / 192;
    int rr = rowall - blk * 192;
    int gate = rr >> 6;
    int dd = rr & 63;
    int g = gate * 256 + blk * 64 + dd;
    float v = (k < 256) ? wih[g * 256 + k] : whh[g * 256 + (k - 256)];
    float hi, lo; split1(v, hi, lo);
    g_Wb[idx] = __float2bfloat16(hi);
    g_Wb[WSTRIDE + idx] = __float2bfloat16(lo);
}

// ---------------- level-0 prep: leaf -> A1 (xL, h=0), A2a (xR) ----------------
__global__ void prep0(const float* __restrict__ emb, int M) {
    int idx = blockIdx.x * blockDim.x + threadIdx.x;   // M*128
    if (idx >= M * 128) return;
    int m = idx >> 7;
    int kq = idx & 127;
    size_t rowL = ((size_t)(2 * m)) * 256;   // lgP=11, n=4096: b*4096+2j = 2m
    char* A1 = (char*)g_A1;
    char* A2 = (char*)g_A2a;
    if (kq < 64) {
        int k = kq * 4;
        float4 xl = *(const float4*)(emb + rowL + k);
        float4 xr = *(const float4*)(emb + rowL + 256 + k);
        uint2 hi, lo;
        size_t off = (size_t)m * 1024 + (size_t)k * 2;
        split4(xl, hi, lo);
        *(uint2*)(A1 + off) = hi;
        *(uint2*)(A1 + ABYTES + off) = lo;
        split4(xr, hi, lo);
        *(uint2*)(A2 + off) = hi;
        *(uint2*)(A2 + ABYTES + off) = lo;
    } else {
        int k = (kq - 64) * 4;
        size_t off = (size_t)m * 1024 + 512 + (size_t)k * 2;
        *(uint2*)(A1 + off) = make_uint2(0u, 0u);
        *(uint2*)(A1 + ABYTES + off) = make_uint2(0u, 0u);
    }
}

// ---------------- GEMM cell kernel ----------------
// smem: 4 staging buffers x 40960B (Ahi 8K | Alo 8K | Whi 12K | Wlo 12K).
// Epilogue overlays 4 gate planes [128][68] f32 (34816B each) at 0,
// ho plane at 139264, bias (256 f32) at 174080.
#define SM_BUFSZ 40960
#define PLANE_B 34816
#define PLANE_F 8704
#define SM_HOPL 139264
#define SM_BIAS 174080
#define SM_TOTAL 175104

template<int MODE>
__global__ __launch_bounds__(512, 1) void gemm_cell(
    const __nv_bfloat16* __restrict__ Abase,
    const float* __restrict__ bih, const float* __restrict__ bhh,
    __nv_bfloat16* __restrict__ Hw,            // MODE0: h1 split dest (A2cur h-part)
    __nv_bfloat16* __restrict__ A1n,           // MODE1: next-level A1 (or null)
    __nv_bfloat16* __restrict__ A2n,           // MODE1: next-level A2
    float* __restrict__ embOut,                // MODE1 level 11 only
    int M)
{
    extern __shared__ char smem[];
    const uint32_t sbt = smem_u32(smem);
    const int t = threadIdx.x;
    const int lane = t & 31, wid = t >> 5;
    const int mi = wid & 3, nb = wid >> 2;     // nb: 0=r 1=z 2=i_n 3=h_n
    const int rowBase = blockIdx.x * 128;
    const int dblk = blockIdx.y;
    const int d0g = dblk * 64;
    const char* Ab = (const char*)Abase;

    // stage combined biases
    if (t < 64) {
        int dg = d0g + t;
        float* bs = (float*)(smem + SM_BIAS);
        bs[t]       = bih[dg] + bhh[dg];
        bs[64 + t]  = bih[256 + dg] + bhh[256 + dg];
        bs[128 + t] = bih[512 + dg];
        bs[192 + t] = bhh[512 + dg];
    }

    // ---- precompute 5 staging slots per thread (2560 x 16B per chunk) ----
    const char *s0, *s1, *s2, *s3, *s4;
    uint32_t dst0, dst1, dst2, dst3, dst4;
    {
        // slots 0,1: A (2 terms x 128 rows x 4 segs)
        #pragma unroll
        for (int p = 0; p < 2; ++p) {
            int u = t + 512 * p;
            int term = u >> 9, rem = u & 511, row = rem >> 2, seg = rem & 3;
            const char* sp = Ab + (size_t)term * ABYTES +
                             (size_t)(rowBase + row) * 1024 + seg * 16;
            uint32_t d = term * 8192 + SW64(row * 64 + seg * 16);
            if (p == 0) { s0 = sp; dst0 = d; } else { s1 = sp; dst1 = d; }
        }
        // slots 2-4: W (2 terms x 192 rows x 4 segs)
        #pragma unroll
        for (int p = 2; p < 5; ++p) {
            int v = t + 512 * p - 1024;
            int term = (v >= 768) ? 1 : 0;
            int rem = v - term * 768, row = rem >> 2, seg = rem & 3;
            const char* sp = (const char*)g_Wb + (size_t)term * WBYTES +
                             (size_t)(dblk * 192 + row) * 1024 + seg * 16;
            uint32_t d = 16384 + term * 12288 + SW64(row * 64 + seg * 16);
            if (p == 2) { s2 = sp; dst2 = d; }
            else if (p == 3) { s3 = sp; dst3 = d; }
            else { s4 = sp; dst4 = d; }
        }
    }
#define STAGE(bi) do { uint32_t bb = sbt + (bi) * SM_BUFSZ;           \
        cpasync16(bb + dst0, s0); s0 += 64;                            \
        cpasync16(bb + dst1, s1); s1 += 64;                            \
        cpasync16(bb + dst2, s2); s2 += 64;                            \
        cpasync16(bb + dst3, s3); s3 += 64;                            \
        cpasync16(bb + dst4, s4); s4 += 64; } while (0)

    // ---- ldsm address precompute ----
    const int rsel = lane & 15, half = lane >> 4;
    const int m0 = mi * 32;
    const int wrow = (nb >= 2) ? 128 : nb * 64;
    const int rA0 = m0 + rsel,      aoff0 = rA0 * 64, ax0 = (rA0 >> 1) & 3;
    const int rA1 = m0 + 16 + rsel, aoff1 = rA1 * 64, ax1 = (rA1 >> 1) & 3;
    int boff[4], bx[4];
    #pragma unroll
    for (int n16 = 0; n16 < 4; ++n16) {
        int rB = wrow + n16 * 16 + rsel;
        boff[n16] = rB * 64;
        bx[n16] = (rB >> 1) & 3;
    }

    float acc[2][8][4];
    #pragma unroll
    for (int a = 0; a < 2; ++a)
        #pragma unroll
        for (int b = 0; b < 8; ++b)
            #pragma unroll
            for (int e = 0; e < 4; ++e) acc[a][b][e] = 0.f;

    STAGE(0); cpcommit();
    STAGE(1); cpcommit();
    STAGE(2); cpcommit();

    for (int c = 0; c < 16; ++c) {
        __syncthreads();                       // buf (c-1)&3 readers done
        if (c < 13) STAGE((c + 3) & 3);
        cpcommit();
        cpwait<3>();
        __syncthreads();                       // chunk c visible to all
        bool act = (nb < 2) || (nb == 2 && c < 8) || (nb == 3 && c >= 8);
        if (act) {
            uint32_t bb = sbt + (c & 3) * SM_BUFSZ;
            uint32_t bA = bb, bAl = bb + 8192, bW = bb + 16384, bWl = bb + 28672;
            #pragma unroll
            for (int kb = 0; kb < 2; ++kb) {
                int sg = 2 * kb + half;
                uint32_t ah[2][4], al[2][4];
                ldsm4(ah[0], bA  + aoff0 + ((sg ^ ax0) << 4));
                ldsm4(ah[1], bA  + aoff1 + ((sg ^ ax1) << 4));
                ldsm4(al[0], bAl + aoff0 + ((sg ^ ax0) << 4));
                ldsm4(al[1], bAl + aoff1 + ((sg ^ ax1) << 4));
                #pragma unroll
                for (int n16 = 0; n16 < 4; ++n16) {
                    uint32_t bh[4], bl[4];
                    uint32_t wo = ((sg ^ bx[n16]) << 4) + boff[n16];
                    ldsm4(bh, bW + wo);
                    ldsm4(bl, bWl + wo);
                    #pragma unroll
                    for (int tm = 0; tm < 2; ++tm) {
                        mma16816(acc[tm][2*n16],   ah[tm], bh[0], bh[2]);
                        mma16816(acc[tm][2*n16+1], ah[tm], bh[1], bh[3]);
                        mma16816(acc[tm][2*n16],   ah[tm], bl[0], bl[2]);
                        mma16816(acc[tm][2*n16+1], ah[tm], bl[1], bl[3]);
                        mma16816(acc[tm][2*n16],   al[tm], bh[0], bh[2]);
                        mma16816(acc[tm][2*n16+1], al[tm], bh[1], bh[3]);
                    }
                }
            }
        }
    }
    __syncthreads();                           // last mma done before overlay

    // ---- store accumulators to gate planes [nb][128][68] ----
    {
        float* plane = (float*)(smem + nb * PLANE_B);
        int r0 = lane >> 2, c0 = (lane & 3) * 2;
        #pragma unroll
        for (int tm = 0; tm < 2; ++tm)
            #pragma unroll
            for (int tn = 0; tn < 8; ++tn) {
                int mrow = m0 + tm * 16 + r0;
                int ncol = tn * 8 + c0;
                *(float2*)(plane + mrow * 68 + ncol) =
                    make_float2(acc[tm][tn][0], acc[tm][tn][1]);
                *(float2*)(plane + (mrow + 8) * 68 + ncol) =
                    make_float2(acc[tm][tn][2], acc[tm][tn][3]);
            }
    }
    __syncthreads();

    // ---- fused GRU epilogue: thread -> (row m = t>>2, 16 dims) ----
    const int m = t >> 2;
    const int dl0 = (t & 3) * 16;
    const int mg = rowBase + m;
    const bool valid = (mg < M);
    float ho16[16], hp16[16];
    if (valid) {
        rsplit16(Ab + (size_t)mg * 1024 + 512 + (size_t)(d0g + dl0) * 2, hp16);
        const float* pf = (const float*)smem;
        const float* bs = (const float*)(smem + SM_BIAS);
        #pragma unroll
        for (int q4 = 0; q4 < 4; ++q4) {
            int dl = dl0 + q4 * 4;
            const float* p0 = pf + m * 68 + dl;
            float4 vr  = *(const float4*)(p0);
            float4 vz  = *(const float4*)(p0 + PLANE_F);
            float4 vni = *(const float4*)(p0 + 2 * PLANE_F);
            float4 vnh = *(const float4*)(p0 + 3 * PLANE_F);
            float ar[4] = {vr.x, vr.y, vr.z, vr.w};
            float az[4] = {vz.x, vz.y, vz.z, vz.w};
            float ai[4] = {vni.x, vni.y, vni.z, vni.w};
            float ah[4] = {vnh.x, vnh.y, vnh.z, vnh.w};
            #pragma unroll
            for (int e = 0; e < 4; ++e) {
                int dq = dl + e;
                float r = sigacc(ar[e] + bs[dq]);
                float z = sigacc(az[e] + bs[64 + dq]);
                float nv = tanhacc(ai[e] + bs[128 + dq] + r * (ah[e] + bs[192 + dq]));
                ho16[q4 * 4 + e] = (1.f - z) * nv + z * hp16[q4 * 4 + e];
            }
        }
    }

    if (MODE == 0) {
        if (valid)
            wsplit16((char*)Hw + (size_t)mg * 1024 + 512 + (size_t)(d0g + dl0) * 2,
                     ho16);
    } else {
        float e16[16];
        if (valid) {
            #pragma unroll
            for (int q = 0; q < 16; ++q) e16[q] = 0.5f * (hp16[q] + ho16[q]);
            if (embOut) {
                #pragma unroll
                for (int q4 = 0; q4 < 4; ++q4)
                    *(float4*)(embOut + (size_t)mg * 256 + d0g + dl0 + q4 * 4) =
                        make_float4(e16[q4*4], e16[q4*4+1], e16[q4*4+2], e16[q4*4+3]);
            }
        }
        if (A1n) {
            float* hop = (float*)(smem + SM_HOPL);
            if (valid) {
                // emb' -> next-level x-part
                __nv_bfloat16* dstA = (m & 1) ? A2n : A1n;
                wsplit16((char*)dstA + (size_t)(mg >> 1) * 1024 +
                         (size_t)(d0g + dl0) * 2, e16);
                // stage h2 for pair exchange
                #pragma unroll
                for (int q4 = 0; q4 < 4; ++q4)
                    *(float4*)(hop + m * 68 + dl0 + q4 * 4) =
                        make_float4(ho16[q4*4], ho16[q4*4+1], ho16[q4*4+2], ho16[q4*4+3]);
            }
            __syncthreads();
            if (valid && !(m & 1)) {
                float h016[16];
                #pragma unroll
                for (int q4 = 0; q4 < 4; ++q4) {
                    float4 v = *(const float4*)(hop + (m + 1) * 68 + dl0 + q4 * 4);
                    h016[q4*4]   = 0.5f * (ho16[q4*4]   + v.x);
                    h016[q4*4+1] = 0.5f * (ho16[q4*4+1] + v.y);
                    h016[q4*4+2] = 0.5f * (ho16[q4*4+2] + v.z);
                    h016[q4*4+3] = 0.5f * (ho16[q4*4+3] + v.w);
                }
                wsplit16((char*)A1n + (size_t)(mg >> 1) * 1024 + 512 +
                         (size_t)(d0g + dl0) * 2, h016);
            }
        }
    }
#undef STAGE
}

// ---------------- driver ----------------
extern "C" void kernel_launch(void* const* d_in, const int* in_sizes, int n_in,
                              void* d_out, int out_size) {
    (void)in_sizes; (void)n_in; (void)out_size;
    const float* leaf = (const float*)d_in[0];
    const float* Wih  = (const float*)d_in[1];
    const float* Whh  = (const float*)d_in[2];
    const float* bih  = (const float*)d_in[3];
    const float* bhh  = (const float*)d_in[4];
    float* out = (float*)d_out;

    __nv_bfloat16 *A1, *A2a, *A2b;
    cudaGetSymbolAddress((void**)&A1, g_A1);
    cudaGetSymbolAddress((void**)&A2a, g_A2a);
    cudaGetSymbolAddress((void**)&A2b, g_A2b);

    cudaFuncSetAttribute(gemm_cell<0>, cudaFuncAttributeMaxDynamicSharedMemorySize, SM_TOTAL);
    cudaFuncSetAttribute(gemm_cell<1>, cudaFuncAttributeMaxDynamicSharedMemorySize, SM_TOTAL);

    wprep<<<(4 * 192 * 512 + 255) / 256, 256>>>(Wih, Whh);
    prep0<<<(65536 * 128) / 256, 256>>>(leaf, 65536);

    __nv_bfloat16* A2cur = A2a;
    for (int lvl = 0; lvl < 12; ++lvl) {
        int M = 32 << (11 - lvl);
        dim3 grid((M + 127) / 128, 4);
        // cell1: reads A1 (x=xL, h=h0); writes h1 split into A2cur h-part
        gemm_cell<0><<<grid, 512, SM_TOTAL>>>(A1, bih, bhh, A2cur,
                                              nullptr, nullptr, nullptr, M);
        // cell2: reads A2cur (x=xR, h=h1); writes next-level A1/A2next (+ out)
        __nv_bfloat16* A2next = (A2cur == A2a) ? A2b : A2a;
        bool last = (lvl == 11);
        gemm_cell<1><<<grid, 512, SM_TOTAL>>>(A2cur, bih, bhh, nullptr,
                                              last ? nullptr : A1,
                                              last ? nullptr : A2next,
                                              last ? out : nullptr, M);
        A2cur = A2next;
    }
}